// round 1
// baseline (speedup 1.0000x reference)
#include <cuda_runtime.h>

#define NTYPES 4
#define NDESC  8
#define KMAX   8
#define LMAX   4
#define MNBR   20
#define NPAIR  (MNBR * (MNBR - 1) / 2)   // 190
#define RCUT   5.0f
#define PI_F   3.14159265358979f

#define WARPS_PER_BLOCK 8
#define THREADS (WARPS_PER_BLOCK * 32)
#define CT_ROWS   (NTYPES * NTYPES)      // 16 rows of 64 floats
#define CT_STRIDE 68                     // padded: 68 % 32 == 4 -> conflict-free across tj rows

__global__ __launch_bounds__(THREADS)
void angular_desc_kernel(const int*   __restrict__ types,
                         const float* __restrict__ positions,
                         const int*   __restrict__ nbrs,
                         const float* __restrict__ c_table,
                         float*       __restrict__ out,
                         int N)
{
    __shared__ float        sh_ct[CT_ROWS * CT_STRIDE];
    __shared__ unsigned int sh_pair[NPAIR];
    __shared__ float4       sh_nbr[WARPS_PER_BLOCK][MNBR * 3];

    const int tid = threadIdx.x;

    // Stage c_table into padded shared (block-wide, once)
    for (int idx = tid; idx < CT_ROWS * 64; idx += THREADS) {
        int row = idx >> 6, col = idx & 63;
        sh_ct[row * CT_STRIDE + col] = c_table[idx];
    }
    // Build pair LUT: all (j<k) pairs packed j | (k<<8)
    for (int p = tid; p < NPAIR; p += THREADS) {
        int j = 0, rem = p;
        while (rem >= MNBR - 1 - j) { rem -= MNBR - 1 - j; j++; }
        int k = j + 1 + rem;
        sh_pair[p] = (unsigned)(j | (k << 8));
    }
    __syncthreads();

    const int warp = tid >> 5;
    const int lane = tid & 31;
    const int atom = blockIdx.x * WARPS_PER_BLOCK + warp;
    if (atom >= N) return;

    const int   ti  = types[atom];
    const float pix = positions[atom * 3 + 0];
    const float piy = positions[atom * 3 + 1];
    const float piz = positions[atom * 3 + 2];

    // ---- Phase 1: per-edge records (lanes 0..19) ----
    if (lane < MNBR) {
        int j = nbrs[atom * MNBR + lane];
        float dx = positions[j * 3 + 0] - pix;
        float dy = positions[j * 3 + 1] - piy;
        float dz = positions[j * 3 + 2] - piz;
        float r  = sqrtf(dx * dx + dy * dy + dz * dz);

        // Chebyshev radial basis: f_k = (T_k(x) + 1) * 0.5 * fc(r)
        float fc  = (r < RCUT) ? (0.5f * __cosf(PI_F * r * (1.0f / RCUT)) + 0.5f) : 0.0f;
        float hfc = 0.5f * fc;
        float xr  = r * (1.0f / RCUT) - 1.0f;
        float x   = 2.0f * xr * xr - 1.0f;
        float fvec[KMAX];
        float tm2 = 1.0f, tm1 = x;
        fvec[0] = (tm2 + 1.0f) * hfc;
        fvec[1] = (tm1 + 1.0f) * hfc;
        #pragma unroll
        for (int k = 2; k < KMAX; k++) {
            float t = 2.0f * x * tm1 - tm2;
            tm2 = tm1; tm1 = t;
            fvec[k] = (t + 1.0f) * hfc;
        }

        int tj = types[j];
        const float* crow = &sh_ct[(ti * NTYPES + tj) * CT_STRIDE];
        float g[NDESC];
        #pragma unroll
        for (int d = 0; d < NDESC; d++) {
            const float4 c0 = *(const float4*)(crow + d * 8);
            const float4 c1 = *(const float4*)(crow + d * 8 + 4);
            g[d] = c0.x * fvec[0] + c0.y * fvec[1] + c0.z * fvec[2] + c0.w * fvec[3]
                 + c1.x * fvec[4] + c1.y * fvec[5] + c1.z * fvec[6] + c1.w * fvec[7];
        }
        sh_nbr[warp][lane * 3 + 0] = make_float4(dx, dy, dz, r);
        sh_nbr[warp][lane * 3 + 1] = make_float4(g[0], g[1], g[2], g[3]);
        sh_nbr[warp][lane * 3 + 2] = make_float4(g[4], g[5], g[6], g[7]);
    }
    __syncwarp();

    // ---- Phase 2: pair loop, per-lane accumulation of full [8][4] tile ----
    float v[32];
    #pragma unroll
    for (int q = 0; q < 32; q++) v[q] = 0.0f;

    for (int p = lane; p < NPAIR; p += 32) {
        unsigned jk = sh_pair[p];
        int j = jk & 0xff;
        int k = (int)(jk >> 8);
        const float4 aj  = sh_nbr[warp][j * 3 + 0];
        const float4 gj0 = sh_nbr[warp][j * 3 + 1];
        const float4 gj1 = sh_nbr[warp][j * 3 + 2];
        const float4 ak  = sh_nbr[warp][k * 3 + 0];
        const float4 gk0 = sh_nbr[warp][k * 3 + 1];
        const float4 gk1 = sh_nbr[warp][k * 3 + 2];

        float dot   = aj.x * ak.x + aj.y * ak.y + aj.z * ak.z;
        float denom = aj.w * ak.w + 1e-8f;
        float c     = __fdividef(dot, denom);

        // Legendre P0..P3
        float p1 = c;
        float p2 = 1.5f * c * c - 0.5f;
        float p3 = (5.0f * c * p2 - 2.0f * p1) * (1.0f / 3.0f);

        float G[NDESC];
        G[0] = gj0.x * gk0.x;  G[1] = gj0.y * gk0.y;
        G[2] = gj0.z * gk0.z;  G[3] = gj0.w * gk0.w;
        G[4] = gj1.x * gk1.x;  G[5] = gj1.y * gk1.y;
        G[6] = gj1.z * gk1.z;  G[7] = gj1.w * gk1.w;

        #pragma unroll
        for (int d = 0; d < NDESC; d++) {
            v[d * 4 + 0] += G[d];                       // P0 = 1
            v[d * 4 + 1] = fmaf(G[d], p1, v[d * 4 + 1]);
            v[d * 4 + 2] = fmaf(G[d], p2, v[d * 4 + 2]);
            v[d * 4 + 3] = fmaf(G[d], p3, v[d * 4 + 3]);
        }
    }

    // ---- Phase 3: butterfly transpose-reduction ----
    // After 5 steps, lane L holds sum over all lanes of original v[L].
    #define RSTEP(M_, HALF_)                                            \
    {                                                                   \
        bool hi = (lane & (M_)) != 0;                                   \
        _Pragma("unroll")                                               \
        for (int k2 = 0; k2 < (HALF_); k2++) {                          \
            float send = hi ? v[k2] : v[k2 + (HALF_)];                  \
            float recv = __shfl_xor_sync(0xffffffffu, send, (M_));      \
            v[k2] = (hi ? v[k2 + (HALF_)] : v[k2]) + recv;              \
        }                                                               \
    }
    RSTEP(16, 16)
    RSTEP(8, 8)
    RSTEP(4, 4)
    RSTEP(2, 2)
    RSTEP(1, 1)
    #undef RSTEP

    // v index = d*4 + l matches out layout [N, NDESC, LMAX]; one coalesced 128B store.
    out[atom * (NDESC * LMAX) + lane] = v[0];
}

extern "C" void kernel_launch(void* const* d_in, const int* in_sizes, int n_in,
                              void* d_out, int out_size)
{
    const int*   types     = (const int*)d_in[0];
    const float* positions = (const float*)d_in[1];
    const int*   nbrs      = (const int*)d_in[2];
    const float* c_table   = (const float*)d_in[3];
    float*       out       = (float*)d_out;

    const int N = in_sizes[0];
    const int blocks = (N + WARPS_PER_BLOCK - 1) / WARPS_PER_BLOCK;
    angular_desc_kernel<<<blocks, THREADS>>>(types, positions, nbrs, c_table, out, N);
}

// round 3
// speedup vs baseline: 1.4812x; 1.4812x over previous
#include <cuda_runtime.h>

#define NTYPES 4
#define NDESC  8
#define KMAX   8
#define LMAX   4
#define MNBR   20
#define RCUT   5.0f
#define PI_F   3.14159265358979f

#define WARPS_PER_BLOCK 8
#define THREADS (WARPS_PER_BLOCK * 32)
#define CT_ROWS   (NTYPES * NTYPES)
#define CT_STRIDE 68                 // 68 % 32 == 4 -> conflict-free across type rows
#define REC_F4    7                  // edge record: 6 float4 used + 1 pad (break STS conflicts)
#define REC_F     (REC_F4 * 4)       // 28 floats

__global__ __launch_bounds__(THREADS)
void angular_desc_kernel(const int*   __restrict__ types,
                         const float* __restrict__ positions,
                         const int*   __restrict__ nbrs,
                         const float* __restrict__ c_table,
                         float*       __restrict__ out,
                         int N)
{
    __shared__ float  sh_ct[CT_ROWS * CT_STRIDE];
    __shared__ float4 sh_e[WARPS_PER_BLOCK][MNBR][REC_F4];

    const int tid = threadIdx.x;

    // Stage c_table into padded shared (block-wide, once)
    for (int idx = tid; idx < CT_ROWS * 64; idx += THREADS) {
        int row = idx >> 6, col = idx & 63;
        sh_ct[row * CT_STRIDE + col] = c_table[idx];
    }
    __syncthreads();

    const int warp = tid >> 5;
    const int lane = tid & 31;
    const int atom = blockIdx.x * WARPS_PER_BLOCK + warp;
    if (atom >= N) return;

    const int   ti  = types[atom];
    const float pix = positions[atom * 3 + 0];
    const float piy = positions[atom * 3 + 1];
    const float piz = positions[atom * 3 + 2];

    // ---- Phase 1: per-edge records (lanes 0..19): g[8] and Z[16] ----
    if (lane < MNBR) {
        int j = nbrs[atom * MNBR + lane];
        float dx = positions[j * 3 + 0] - pix;
        float dy = positions[j * 3 + 1] - piy;
        float dz = positions[j * 3 + 2] - piz;
        float n2   = dx * dx + dy * dy + dz * dz;
        float inv  = rsqrtf(n2);
        float r    = n2 * inv;
        float x = dx * inv, y = dy * inv, z = dz * inv;

        // Chebyshev radial basis: f_k = (T_k(x)+1) * 0.5*fc(r)
        float fc  = (r < RCUT) ? (0.5f * __cosf(PI_F * r * (1.0f / RCUT)) + 0.5f) : 0.0f;
        float hfc = 0.5f * fc;
        float xr  = r * (1.0f / RCUT) - 1.0f;
        float xc  = 2.0f * xr * xr - 1.0f;
        float fvec[KMAX];
        float tm2 = 1.0f, tm1 = xc;
        fvec[0] = (tm2 + 1.0f) * hfc;
        fvec[1] = (tm1 + 1.0f) * hfc;
        #pragma unroll
        for (int k = 2; k < KMAX; k++) {
            float t = 2.0f * xc * tm1 - tm2;
            tm2 = tm1; tm1 = t;
            fvec[k] = (t + 1.0f) * hfc;
        }

        int tj = types[j];
        const float* crow = &sh_ct[(ti * NTYPES + tj) * CT_STRIDE];
        float g[NDESC];
        #pragma unroll
        for (int d = 0; d < NDESC; d++) {
            const float4 c0 = *(const float4*)(crow + d * 8);
            const float4 c1 = *(const float4*)(crow + d * 8 + 4);
            g[d] = c0.x * fvec[0] + c0.y * fvec[1] + c0.z * fvec[2] + c0.w * fvec[3]
                 + c1.x * fvec[4] + c1.y * fvec[5] + c1.z * fvec[6] + c1.w * fvec[7];
        }

        // Real spherical harmonics Z_lm scaled so P_l(u.v) = sum_m Z_lm(u) Z_lm(v)
        float x2 = x * x, y2 = y * y, z2 = z * z;
        const float SQ3  = 1.73205080757f;
        const float SQ3H = 0.86602540378f;
        const float C31  = 0.61237243570f;   // sqrt(6)/4
        const float C32a = 3.87298334621f;   // sqrt(15)
        const float C32b = 1.93649167310f;   // sqrt(15)/2
        const float C33  = 0.79056941504f;   // sqrt(10)/4
        float a5z = 5.0f * z2 - 1.0f;

        float4 zA = make_float4(1.0f, x, y, z);
        float4 zB = make_float4(SQ3 * x * y, SQ3 * y * z, SQ3 * x * z, SQ3H * (x2 - y2));
        float4 zC = make_float4(0.5f * (3.0f * z2 - 1.0f),
                                C33 * y * (3.0f * x2 - y2),
                                C32a * x * y * z,
                                C31 * y * a5z);
        float4 zD = make_float4(0.5f * z * (5.0f * z2 - 3.0f),
                                C31 * x * a5z,
                                C32b * z * (x2 - y2),
                                C33 * x * (x2 - 3.0f * y2));

        sh_e[warp][lane][0] = make_float4(g[0], g[1], g[2], g[3]);
        sh_e[warp][lane][1] = make_float4(g[4], g[5], g[6], g[7]);
        sh_e[warp][lane][2] = zA;
        sh_e[warp][lane][3] = zB;
        sh_e[warp][lane][4] = zC;
        sh_e[warp][lane][5] = zD;
    }
    __syncwarp();

    // ---- Phase 2: S[d][m] = sum_j g_d(j) Z_m(j). lane: d = lane&7, mgroup = lane>>3 ----
    const int d  = lane & 7;
    const int mg = lane >> 3;
    const float* rec = (const float*)&sh_e[warp][0][0];

    float S0 = 0.0f, S1 = 0.0f, S2 = 0.0f, S3 = 0.0f, gg = 0.0f;
    #pragma unroll
    for (int j = 0; j < MNBR; j++) {
        const float* base = rec + j * REC_F;
        float gv = base[d];                       // broadcast across lanes sharing d
        float4 zv = *(const float4*)(base + 8 + 4 * mg);  // uniform j -> conflict-free
        S0 = fmaf(gv, zv.x, S0);
        S1 = fmaf(gv, zv.y, S1);
        S2 = fmaf(gv, zv.z, S2);
        S3 = fmaf(gv, zv.w, S3);
        gg = fmaf(gv, gv, gg);
    }

    // Partial sums of squares split by l within each m-group:
    // mg0: m0(l0) | m1..3(l1);  mg1: m4..7(l2);  mg2: m8(l2) | m9..11(l3);  mg3: m12..15(l3)
    float PA, PB;
    if (mg == 0 || mg == 2) {
        PA = S0 * S0;
        PB = S1 * S1 + S2 * S2 + S3 * S3;
    } else {
        PA = S0 * S0 + S1 * S1 + S2 * S2 + S3 * S3;
        PB = 0.0f;
    }

    // ---- Phase 3: recombine to output lane (do = lane>>2, lo = lane&3) ----
    const int lo = lane & 3;
    const int od = lane >> 2;

    int srcA = (lo == 0) ? od : (lo == 2) ? (8 + od) : (lo == 3) ? (24 + od) : od;
    float vA = __shfl_sync(0xffffffffu, PA, srcA);
    int srcB = (lo == 1) ? od : (16 + od);
    float vB = __shfl_sync(0xffffffffu, PB, srcB);
    float vC = __shfl_sync(0xffffffffu, PA, 16 + od);
    float ggv = __shfl_sync(0xffffffffu, gg, od);   // lane od computed d=od

    float sumsq;
    if      (lo == 0) sumsq = vA;
    else if (lo == 1) sumsq = vB;
    else if (lo == 2) sumsq = vA + vC;
    else              sumsq = vA + vB;

    out[atom * (NDESC * LMAX) + lane] = 0.5f * (sumsq - ggv);
}

extern "C" void kernel_launch(void* const* d_in, const int* in_sizes, int n_in,
                              void* d_out, int out_size)
{
    const int*   types     = (const int*)d_in[0];
    const float* positions = (const float*)d_in[1];
    const int*   nbrs      = (const int*)d_in[2];
    const float* c_table   = (const float*)d_in[3];
    float*       out       = (float*)d_out;

    const int N = in_sizes[0];
    const int blocks = (N + WARPS_PER_BLOCK - 1) / WARPS_PER_BLOCK;
    angular_desc_kernel<<<blocks, THREADS>>>(types, positions, nbrs, c_table, out, N);
}